// round 10
// baseline (speedup 1.0000x reference)
#include <cuda_runtime.h>
#include <cstdint>

#define N_NODES 50000
#define MAXE    800000
#define D       64
#define CAP     128   // max in-degree capacity (E/N=16, Poisson tail @128 ~ 1e-60)

// ---- scratch (device globals; zero-initialized at module load) ----
// INVARIANT: g_count is all-zero at kernel_launch entry; fused_kernel restores
// this before exiting, so every graph replay sees zeros.
__device__ int   g_count[N_NODES];        // in-degree
__device__ int2  g_edges[N_NODES * CAP];  // direct-placed (edge_id, src) records
__device__ float g_WmT[128 * 64];         // W_msg transposed+paired
__device__ float g_WaT[128 * 64];         // W_apply transposed+paired

// ---------------------------------------------------------------------------
// K1: build = histogram + direct placement; first 8K threads also transpose
// weights into paired layout WT[k*64 + (o&31)*2 + (o>>5)] = W[o*128+k].
// ---------------------------------------------------------------------------
__global__ void build_kernel(const int* __restrict__ src,
                             const int* __restrict__ dst, int E,
                             const float* __restrict__ W_msg,
                             const float* __restrict__ W_apply) {
    int e = blockIdx.x * blockDim.x + threadIdx.x;
    if (e < 64 * 128) {
        int o = e >> 7, k = e & 127;
        int slot = k * 64 + (o & 31) * 2 + (o >> 5);
        g_WmT[slot] = W_msg[e];
        g_WaT[slot] = W_apply[e];
    }
    if (e >= E) return;
    int d = dst[e];
    int r = atomicAdd(&g_count[d], 1);
    if (r < CAP) g_edges[(size_t)d * CAP + r] = make_int2(e, src[e]);
}

// ---------------------------------------------------------------------------
// K2: FUSED gather + node update. SMEM = z only (40KB) -> 4 blocks/SM.
// Gather pipelines the next node's edge-record chunk behind the current
// node's feature-load chain. Weights via coalesced LDG.64 (L1-resident).
// At the end each warp zeroes its own nodes' counters (restores invariant).
// ---------------------------------------------------------------------------
#define ZSTRIDE 10
#define WPB 8
#define NPW 8
#define NPB (WPB * NPW)

#define PACK2(dst, f) asm("mov.b64 %0, {%1,%1};" : "=l"(dst) : "r"(__float_as_uint(f)))
#define UNPACK2(lo, hi, src) asm("mov.b64 {%0,%1}, %2;" : "=r"(lo), "=r"(hi) : "l"(src))
#define FMA2(acc, a, b) asm("fma.rn.f32x2 %0, %1, %2, %0;" : "+l"(acc) : "l"(a), "l"(b))
#define ACC4(A, T) {A.x += T.x; A.y += T.y; A.z += T.z; A.w += T.w;}

__device__ __forceinline__ void accum_chunk(int2 rec, int n, bool isN, int q,
                                            const float* __restrict__ fbase,
                                            float4& acc0, float4& acc1) {
    int jj = 0;
    #pragma unroll 1
    for (; jj + 4 <= n; jj += 4) {
        int idx[4];
        #pragma unroll
        for (int u = 0; u < 4; u++) {
            int x = __shfl_sync(0xffffffffu, rec.x, jj + u);
            int y = __shfl_sync(0xffffffffu, rec.y, jj + u);
            idx[u] = isN ? y : x;
        }
        const float4* p0 = (const float4*)(fbase + (size_t)idx[0] * D) + q;
        const float4* p1 = (const float4*)(fbase + (size_t)idx[1] * D) + q;
        const float4* p2 = (const float4*)(fbase + (size_t)idx[2] * D) + q;
        const float4* p3 = (const float4*)(fbase + (size_t)idx[3] * D) + q;
        float4 t0 = isN ? __ldg(p0) : __ldcs(p0);
        float4 t1 = isN ? __ldg(p1) : __ldcs(p1);
        float4 t2 = isN ? __ldg(p2) : __ldcs(p2);
        float4 t3 = isN ? __ldg(p3) : __ldcs(p3);
        ACC4(acc0, t0);
        ACC4(acc1, t1);
        ACC4(acc0, t2);
        ACC4(acc1, t3);
    }
    #pragma unroll 1
    for (; jj < n; jj++) {
        int x0 = __shfl_sync(0xffffffffu, rec.x, jj);
        int y0 = __shfl_sync(0xffffffffu, rec.y, jj);
        const float4* p = (const float4*)(fbase + (size_t)(isN ? y0 : x0) * D) + q;
        float4 a = isN ? __ldg(p) : __ldcs(p);
        ACC4(acc0, a);
    }
}

__global__ __launch_bounds__(256, 4)
void fused_kernel(const float* __restrict__ nfeats,
                  const float* __restrict__ efeats,
                  const float* __restrict__ b_msg,
                  const float* __restrict__ b_apply,
                  float* __restrict__ out) {
    extern __shared__ float zb[];         // WPB * [128][ZSTRIDE]

    int tid = threadIdx.x;
    int lane = tid & 31;
    int wid = tid >> 5;

    float* z = zb + wid * (128 * ZSTRIDE);
    int base = blockIdx.x * NPB + wid * NPW;
    int q = lane & 15;
    bool isN = lane < 16;
    const float* fbase = isN ? nfeats : efeats;

    // ---- Gather phase: 8 nodes/warp, rec chunks pipelined one node ahead ----
    int vcur = base < N_NODES ? base : N_NODES - 1;
    int cnt_n = __ldg(&g_count[vcur]);
    if (cnt_n > CAP) cnt_n = CAP;
    int2 rec_n = make_int2(0, 0);
    if (lane < cnt_n) rec_n = __ldg(&g_edges[(size_t)vcur * CAP + lane]);

    #pragma unroll 1
    for (int j = 0; j < NPW; j++) {
        int cnt = cnt_n;
        int2 rec = rec_n;
        size_t start = (size_t)vcur * CAP;

        // prefetch next node's first chunk (hides rec latency behind accum)
        if (j + 1 < NPW) {
            int vn = base + j + 1;
            if (vn >= N_NODES) vn = N_NODES - 1;
            cnt_n = __ldg(&g_count[vn]);
            if (cnt_n > CAP) cnt_n = CAP;
            rec_n = make_int2(0, 0);
            if (lane < cnt_n) rec_n = __ldg(&g_edges[(size_t)vn * CAP + lane]);
            vcur = vn;
        }

        float4 acc0 = make_float4(0.f, 0.f, 0.f, 0.f);
        float4 acc1 = make_float4(0.f, 0.f, 0.f, 0.f);

        int n0 = cnt < 32 ? cnt : 32;
        accum_chunk(rec, n0, isN, q, fbase, acc0, acc1);
        // rare tail: nodes with degree > 32
        #pragma unroll 1
        for (int b0 = 32; b0 < cnt; b0 += 32) {
            int n = cnt - b0;
            if (n > 32) n = 32;
            int2 r2 = make_int2(0, 0);
            if (lane < n) r2 = __ldg(&g_edges[start + b0 + lane]);
            accum_chunk(r2, n, isN, q, fbase, acc0, acc1);
        }

        acc0.x += acc1.x; acc0.y += acc1.y; acc0.z += acc1.z; acc0.w += acc1.w;
        int rowbase = (isN ? 0 : 64) + q * 4;
        z[(rowbase + 0) * ZSTRIDE + j] = acc0.x;
        z[(rowbase + 1) * ZSTRIDE + j] = acc0.y;
        z[(rowbase + 2) * ZSTRIDE + j] = acc0.z;
        z[(rowbase + 3) * ZSTRIDE + j] = acc0.w;
    }
    __syncwarp();

    // ---- Phase A GEMM: msg linear on [Sn ; Se]; weights via LDG (L1) ----
    unsigned long long acc[2][4];
    #pragma unroll
    for (int g = 0; g < 2; g++)
        #pragma unroll
        for (int p = 0; p < 4; p++) acc[g][p] = 0ull;

    #pragma unroll 4
    for (int k = 0; k < 128; k++) {
        float2 wp = __ldg((const float2*)(g_WmT + k * 64) + lane);
        unsigned long long w0p, w1p;
        PACK2(w0p, wp.x);
        PACK2(w1p, wp.y);
        const unsigned long long* zr = (const unsigned long long*)(z + k * ZSTRIDE);
        #pragma unroll
        for (int p = 0; p < 4; p++) {
            unsigned long long s2 = zr[p];
            FMA2(acc[0][p], w0p, s2);
            FMA2(acc[1][p], w1p, s2);
        }
    }
    __syncwarp();

    // ---- h_neigh (mean + bias) + rebuild z for Phase B ----
    float bm0 = b_msg[lane], bm1 = b_msg[lane + 32];
    #pragma unroll
    for (int p = 0; p < 4; p++) {
        int v0 = base + 2 * p, v1 = base + 2 * p + 1;
        int c0 = v0 < N_NODES ? v0 : N_NODES - 1;
        int c1 = v1 < N_NODES ? v1 : N_NODES - 1;
        float d0 = (float)g_count[c0];
        float d1 = (float)g_count[c1];
        float i0 = d0 > 0.f ? 1.f / d0 : 0.f;
        float i1 = d1 > 0.f ? 1.f / d1 : 0.f;
        unsigned ux, uy;
        UNPACK2(ux, uy, acc[0][p]);
        float a0x = __uint_as_float(ux), a0y = __uint_as_float(uy);
        UNPACK2(ux, uy, acc[1][p]);
        float a1x = __uint_as_float(ux), a1y = __uint_as_float(uy);
        z[(64 + lane) * ZSTRIDE + 2 * p]     = d0 > 0.f ? a0x * i0 + bm0 : 0.f;
        z[(64 + lane) * ZSTRIDE + 2 * p + 1] = d1 > 0.f ? a0y * i1 + bm0 : 0.f;
        z[(96 + lane) * ZSTRIDE + 2 * p]     = d0 > 0.f ? a1x * i0 + bm1 : 0.f;
        z[(96 + lane) * ZSTRIDE + 2 * p + 1] = d1 > 0.f ? a1y * i1 + bm1 : 0.f;
    }
    #pragma unroll
    for (int j = 0; j < NPW; j++) {
        int v = base + j;
        if (v >= N_NODES) v = N_NODES - 1;
        const float* nf = nfeats + (size_t)v * D;
        z[(lane)      * ZSTRIDE + j] = nf[lane];
        z[(lane + 32) * ZSTRIDE + j] = nf[lane + 32];
    }
    __syncwarp();

    // restore the zero-counter invariant for the next graph replay
    // (after this warp's last read of its own counters; clamped reads of the
    //  tail node by non-owner warps only feed discarded lanes)
    if (lane < NPW) {
        int v0 = base + lane;
        if (v0 < N_NODES) g_count[v0] = 0;
    }

    // ---- Phase B GEMM: apply linear on [self ; hn] ----
    #pragma unroll
    for (int g = 0; g < 2; g++)
        #pragma unroll
        for (int p = 0; p < 4; p++) acc[g][p] = 0ull;

    #pragma unroll 4
    for (int k = 0; k < 128; k++) {
        float2 wp = __ldg((const float2*)(g_WaT + k * 64) + lane);
        unsigned long long w0p, w1p;
        PACK2(w0p, wp.x);
        PACK2(w1p, wp.y);
        const unsigned long long* zr = (const unsigned long long*)(z + k * ZSTRIDE);
        #pragma unroll
        for (int p = 0; p < 4; p++) {
            unsigned long long s2 = zr[p];
            FMA2(acc[0][p], w0p, s2);
            FMA2(acc[1][p], w1p, s2);
        }
    }

    // ---- Epilogue: bias + relu + store ----
    float ba0 = b_apply[lane], ba1 = b_apply[lane + 32];
    #pragma unroll
    for (int p = 0; p < 4; p++) {
        int v0 = base + 2 * p, v1 = base + 2 * p + 1;
        unsigned ux, uy;
        UNPACK2(ux, uy, acc[0][p]);
        float a0x = __uint_as_float(ux), a0y = __uint_as_float(uy);
        UNPACK2(ux, uy, acc[1][p]);
        float a1x = __uint_as_float(ux), a1y = __uint_as_float(uy);
        if (v0 < N_NODES) {
            out[(size_t)v0 * D + lane]      = fmaxf(a0x + ba0, 0.f);
            out[(size_t)v0 * D + lane + 32] = fmaxf(a1x + ba1, 0.f);
        }
        if (v1 < N_NODES) {
            out[(size_t)v1 * D + lane]      = fmaxf(a0y + ba0, 0.f);
            out[(size_t)v1 * D + lane + 32] = fmaxf(a1y + ba1, 0.f);
        }
    }
}

// ---------------------------------------------------------------------------
#define NODE_SMEM ((WPB * 128 * ZSTRIDE) * (int)sizeof(float))

extern "C" void kernel_launch(void* const* d_in, const int* in_sizes, int n_in,
                              void* d_out, int out_size) {
    const float* nfeats  = (const float*)d_in[0];
    const float* efeats  = (const float*)d_in[1];
    const int*   src     = (const int*)d_in[2];
    const int*   dst     = (const int*)d_in[3];
    const float* W_msg   = (const float*)d_in[4];
    const float* b_msg   = (const float*)d_in[5];
    const float* W_apply = (const float*)d_in[6];
    const float* b_apply = (const float*)d_in[7];
    float* out = (float*)d_out;
    int E = in_sizes[2];

    cudaFuncSetAttribute(fused_kernel, cudaFuncAttributeMaxDynamicSharedMemorySize,
                         NODE_SMEM);

    build_kernel<<<(E + 255) / 256, 256>>>(src, dst, E, W_msg, W_apply);
    int nblocks = (N_NODES + NPB - 1) / NPB;
    fused_kernel<<<nblocks, 256, NODE_SMEM>>>(nfeats, efeats, b_msg, b_apply, out);
}

// round 11
// speedup vs baseline: 1.3341x; 1.3341x over previous
#include <cuda_runtime.h>
#include <cstdint>

#define N_NODES 50000
#define MAXE    800000
#define D       64
#define CAP     128   // max in-degree capacity (E/N=16, Poisson tail @128 ~ 1e-60)

// ---- scratch (device globals; no allocation allowed) ----
__device__ int   g_count[N_NODES];        // in-degree (memset to 0 each launch)
__device__ int2  g_edges[N_NODES * CAP];  // direct-placed (edge_id, src) records
__device__ float g_WmT[128 * 64];         // W_msg transposed+paired
__device__ float g_WaT[128 * 64];         // W_apply transposed+paired

// ---------------------------------------------------------------------------
// K1: build = histogram + direct placement; first 8K threads also transpose
// weights into paired layout WT[k*64 + (o&31)*2 + (o>>5)] = W[o*128+k].
// ---------------------------------------------------------------------------
__global__ void build_kernel(const int* __restrict__ src,
                             const int* __restrict__ dst, int E,
                             const float* __restrict__ W_msg,
                             const float* __restrict__ W_apply) {
    int e = blockIdx.x * blockDim.x + threadIdx.x;
    if (e < 64 * 128) {
        int o = e >> 7, k = e & 127;
        int slot = k * 64 + (o & 31) * 2 + (o >> 5);
        g_WmT[slot] = W_msg[e];
        g_WaT[slot] = W_apply[e];
    }
    if (e >= E) return;
    int d = dst[e];
    int r = atomicAdd(&g_count[d], 1);
    if (r < CAP) g_edges[(size_t)d * CAP + r] = make_int2(e, src[e]);
}

// ---------------------------------------------------------------------------
// K2: FUSED gather + node update (exact R9 body — the 119.4us champion).
// SMEM = z only (40KB) -> 4 blocks/SM. Weights via coalesced LDG.64 (L1-hit).
// Block = 8 warps = 64 nodes; warp gathers 8 nodes' sums into transposed z,
// then runs two register-tiled FFMA2 GEMMs (msg -> mean+bias -> apply -> relu).
// ---------------------------------------------------------------------------
#define ZSTRIDE 10
#define WPB 8
#define NPW 8
#define NPB (WPB * NPW)

#define PACK2(dst, f) asm("mov.b64 %0, {%1,%1};" : "=l"(dst) : "r"(__float_as_uint(f)))
#define UNPACK2(lo, hi, src) asm("mov.b64 {%0,%1}, %2;" : "=r"(lo), "=r"(hi) : "l"(src))
#define FMA2(acc, a, b) asm("fma.rn.f32x2 %0, %1, %2, %0;" : "+l"(acc) : "l"(a), "l"(b))
#define ACC4(A, T) {A.x += T.x; A.y += T.y; A.z += T.z; A.w += T.w;}

__global__ __launch_bounds__(256, 4)
void fused_kernel(const float* __restrict__ nfeats,
                  const float* __restrict__ efeats,
                  const float* __restrict__ b_msg,
                  const float* __restrict__ b_apply,
                  float* __restrict__ out) {
    extern __shared__ float zb[];         // WPB * [128][ZSTRIDE]

    int tid = threadIdx.x;
    int lane = tid & 31;
    int wid = tid >> 5;

    float* z = zb + wid * (128 * ZSTRIDE);
    int base = blockIdx.x * NPB + wid * NPW;
    int q = lane & 15;
    bool isN = lane < 16;
    const float* fbase = isN ? nfeats : efeats;

    // ---- Gather phase: 8 nodes per warp, sums written straight into z ----
    #pragma unroll 1
    for (int j = 0; j < NPW; j++) {
        int v = base + j;
        if (v >= N_NODES) v = N_NODES - 1;
        size_t start = (size_t)v * CAP;
        int cnt = __ldg(&g_count[v]);
        if (cnt > CAP) cnt = CAP;

        float4 acc0 = make_float4(0.f, 0.f, 0.f, 0.f);
        float4 acc1 = make_float4(0.f, 0.f, 0.f, 0.f);

        #pragma unroll 1
        for (int b0 = 0; b0 < cnt; b0 += 32) {
            int n = cnt - b0;
            if (n > 32) n = 32;
            int2 rec = make_int2(0, 0);
            if (lane < n) rec = __ldg(&g_edges[start + b0 + lane]);
            int jj = 0;
            #pragma unroll 1
            for (; jj + 4 <= n; jj += 4) {
                int idx[4];
                #pragma unroll
                for (int u = 0; u < 4; u++) {
                    int x = __shfl_sync(0xffffffffu, rec.x, jj + u);
                    int y = __shfl_sync(0xffffffffu, rec.y, jj + u);
                    idx[u] = isN ? y : x;
                }
                float4 t0, t1, t2, t3;
                {
                    const float4* p0 = (const float4*)(fbase + (size_t)idx[0] * D) + q;
                    const float4* p1 = (const float4*)(fbase + (size_t)idx[1] * D) + q;
                    const float4* p2 = (const float4*)(fbase + (size_t)idx[2] * D) + q;
                    const float4* p3 = (const float4*)(fbase + (size_t)idx[3] * D) + q;
                    t0 = isN ? __ldg(p0) : __ldcs(p0);
                    t1 = isN ? __ldg(p1) : __ldcs(p1);
                    t2 = isN ? __ldg(p2) : __ldcs(p2);
                    t3 = isN ? __ldg(p3) : __ldcs(p3);
                }
                ACC4(acc0, t0);
                ACC4(acc1, t1);
                ACC4(acc0, t2);
                ACC4(acc1, t3);
            }
            #pragma unroll 1
            for (; jj < n; jj++) {
                int x0 = __shfl_sync(0xffffffffu, rec.x, jj);
                int y0 = __shfl_sync(0xffffffffu, rec.y, jj);
                const float4* p = (const float4*)(fbase + (size_t)(isN ? y0 : x0) * D) + q;
                float4 a = isN ? __ldg(p) : __ldcs(p);
                ACC4(acc0, a);
            }
        }
        acc0.x += acc1.x; acc0.y += acc1.y; acc0.z += acc1.z; acc0.w += acc1.w;
        int rowbase = (isN ? 0 : 64) + q * 4;
        z[(rowbase + 0) * ZSTRIDE + j] = acc0.x;
        z[(rowbase + 1) * ZSTRIDE + j] = acc0.y;
        z[(rowbase + 2) * ZSTRIDE + j] = acc0.z;
        z[(rowbase + 3) * ZSTRIDE + j] = acc0.w;
    }
    __syncwarp();

    // ---- Phase A GEMM: msg linear on [Sn ; Se]; weights via LDG (L1) ----
    unsigned long long acc[2][4];
    #pragma unroll
    for (int g = 0; g < 2; g++)
        #pragma unroll
        for (int p = 0; p < 4; p++) acc[g][p] = 0ull;

    #pragma unroll 4
    for (int k = 0; k < 128; k++) {
        float2 wp = __ldg((const float2*)(g_WmT + k * 64) + lane);
        unsigned long long w0p, w1p;
        PACK2(w0p, wp.x);
        PACK2(w1p, wp.y);
        const unsigned long long* zr = (const unsigned long long*)(z + k * ZSTRIDE);
        #pragma unroll
        for (int p = 0; p < 4; p++) {
            unsigned long long s2 = zr[p];
            FMA2(acc[0][p], w0p, s2);
            FMA2(acc[1][p], w1p, s2);
        }
    }
    __syncwarp();

    // ---- h_neigh (mean + bias) + rebuild z for Phase B ----
    float bm0 = b_msg[lane], bm1 = b_msg[lane + 32];
    #pragma unroll
    for (int p = 0; p < 4; p++) {
        int v0 = base + 2 * p, v1 = base + 2 * p + 1;
        int c0 = v0 < N_NODES ? v0 : N_NODES - 1;
        int c1 = v1 < N_NODES ? v1 : N_NODES - 1;
        float d0 = (float)g_count[c0];
        float d1 = (float)g_count[c1];
        float i0 = d0 > 0.f ? 1.f / d0 : 0.f;
        float i1 = d1 > 0.f ? 1.f / d1 : 0.f;
        unsigned ux, uy;
        UNPACK2(ux, uy, acc[0][p]);
        float a0x = __uint_as_float(ux), a0y = __uint_as_float(uy);
        UNPACK2(ux, uy, acc[1][p]);
        float a1x = __uint_as_float(ux), a1y = __uint_as_float(uy);
        z[(64 + lane) * ZSTRIDE + 2 * p]     = d0 > 0.f ? a0x * i0 + bm0 : 0.f;
        z[(64 + lane) * ZSTRIDE + 2 * p + 1] = d1 > 0.f ? a0y * i1 + bm0 : 0.f;
        z[(96 + lane) * ZSTRIDE + 2 * p]     = d0 > 0.f ? a1x * i0 + bm1 : 0.f;
        z[(96 + lane) * ZSTRIDE + 2 * p + 1] = d1 > 0.f ? a1y * i1 + bm1 : 0.f;
    }
    #pragma unroll
    for (int j = 0; j < NPW; j++) {
        int v = base + j;
        if (v >= N_NODES) v = N_NODES - 1;
        const float* nf = nfeats + (size_t)v * D;
        z[(lane)      * ZSTRIDE + j] = nf[lane];
        z[(lane + 32) * ZSTRIDE + j] = nf[lane + 32];
    }
    __syncwarp();

    // ---- Phase B GEMM: apply linear on [self ; hn] ----
    #pragma unroll
    for (int g = 0; g < 2; g++)
        #pragma unroll
        for (int p = 0; p < 4; p++) acc[g][p] = 0ull;

    #pragma unroll 4
    for (int k = 0; k < 128; k++) {
        float2 wp = __ldg((const float2*)(g_WaT + k * 64) + lane);
        unsigned long long w0p, w1p;
        PACK2(w0p, wp.x);
        PACK2(w1p, wp.y);
        const unsigned long long* zr = (const unsigned long long*)(z + k * ZSTRIDE);
        #pragma unroll
        for (int p = 0; p < 4; p++) {
            unsigned long long s2 = zr[p];
            FMA2(acc[0][p], w0p, s2);
            FMA2(acc[1][p], w1p, s2);
        }
    }

    // ---- Epilogue: bias + relu + store ----
    float ba0 = b_apply[lane], ba1 = b_apply[lane + 32];
    #pragma unroll
    for (int p = 0; p < 4; p++) {
        int v0 = base + 2 * p, v1 = base + 2 * p + 1;
        unsigned ux, uy;
        UNPACK2(ux, uy, acc[0][p]);
        float a0x = __uint_as_float(ux), a0y = __uint_as_float(uy);
        UNPACK2(ux, uy, acc[1][p]);
        float a1x = __uint_as_float(ux), a1y = __uint_as_float(uy);
        if (v0 < N_NODES) {
            out[(size_t)v0 * D + lane]      = fmaxf(a0x + ba0, 0.f);
            out[(size_t)v0 * D + lane + 32] = fmaxf(a1x + ba1, 0.f);
        }
        if (v1 < N_NODES) {
            out[(size_t)v1 * D + lane]      = fmaxf(a0y + ba0, 0.f);
            out[(size_t)v1 * D + lane + 32] = fmaxf(a1y + ba1, 0.f);
        }
    }
}

// ---------------------------------------------------------------------------
#define NODE_SMEM ((WPB * 128 * ZSTRIDE) * (int)sizeof(float))

extern "C" void kernel_launch(void* const* d_in, const int* in_sizes, int n_in,
                              void* d_out, int out_size) {
    const float* nfeats  = (const float*)d_in[0];
    const float* efeats  = (const float*)d_in[1];
    const int*   src     = (const int*)d_in[2];
    const int*   dst     = (const int*)d_in[3];
    const float* W_msg   = (const float*)d_in[4];
    const float* b_msg   = (const float*)d_in[5];
    const float* W_apply = (const float*)d_in[6];
    const float* b_apply = (const float*)d_in[7];
    float* out = (float*)d_out;
    int E = in_sizes[2];

    cudaFuncSetAttribute(fused_kernel, cudaFuncAttributeMaxDynamicSharedMemorySize,
                         NODE_SMEM);

    void* cnt_ptr = nullptr;
    cudaGetSymbolAddress(&cnt_ptr, g_count);
    cudaMemsetAsync(cnt_ptr, 0, N_NODES * sizeof(int));

    build_kernel<<<(E + 255) / 256, 256>>>(src, dst, E, W_msg, W_apply);
    int nblocks = (N_NODES + NPB - 1) / NPB;
    fused_kernel<<<nblocks, 256, NODE_SMEM>>>(nfeats, efeats, b_msg, b_apply, out);
}

// round 12
// speedup vs baseline: 1.3847x; 1.0380x over previous
#include <cuda_runtime.h>
#include <cstdint>

#define N_NODES 50000
#define MAXE    800000
#define D       64
#define CAP     128   // max in-degree capacity (E/N=16, Poisson tail @128 ~ 1e-60)

// ---- scratch (device globals; no allocation allowed) ----
__device__ int   g_count[N_NODES];        // in-degree (memset to 0 each launch)
__device__ int2  g_edges[N_NODES * CAP];  // direct-placed (edge_id, src) records
__device__ float g_WmT[128 * 64];         // W_msg transposed+paired
__device__ float g_WaT[128 * 64];         // W_apply transposed+paired

// ---------------------------------------------------------------------------
// K1: build = histogram + direct placement; first 8K threads also transpose
// weights into paired layout WT[k*64 + (o&31)*2 + (o>>5)] = W[o*128+k].
// ---------------------------------------------------------------------------
__global__ void build_kernel(const int* __restrict__ src,
                             const int* __restrict__ dst, int E,
                             const float* __restrict__ W_msg,
                             const float* __restrict__ W_apply) {
    int e = blockIdx.x * blockDim.x + threadIdx.x;
    if (e < 64 * 128) {
        int o = e >> 7, k = e & 127;
        int slot = k * 64 + (o & 31) * 2 + (o >> 5);
        g_WmT[slot] = W_msg[e];
        g_WaT[slot] = W_apply[e];
    }
    if (e >= E) return;
    int d = dst[e];
    int r = atomicAdd(&g_count[d], 1);
    if (r < CAP) g_edges[(size_t)d * CAP + r] = make_int2(e, src[e]);
}

// ---------------------------------------------------------------------------
// K2: FUSED gather + node update.
// Change vs R11 (the 117us champion): gather edge-records are staged through
// the UNUSED z-padding columns (ZSTRIDE=10, only 8 used) in 2 rounds of 4
// nodes — 4 independent LDG.64s per round (one exposed DRAM latency instead
// of one per node), then index reads become 29-cyc LDS broadcasts instead of
// shfl-on-a-just-loaded-register. Everything else byte-identical.
// ---------------------------------------------------------------------------
#define ZSTRIDE 10
#define WPB 8
#define NPW 8
#define NPB (WPB * NPW)

#define PACK2(dst, f) asm("mov.b64 %0, {%1,%1};" : "=l"(dst) : "r"(__float_as_uint(f)))
#define UNPACK2(lo, hi, src) asm("mov.b64 {%0,%1}, %2;" : "=r"(lo), "=r"(hi) : "l"(src))
#define FMA2(acc, a, b) asm("fma.rn.f32x2 %0, %1, %2, %0;" : "+l"(acc) : "l"(a), "l"(b))
#define ACC4(A, T) {A.x += T.x; A.y += T.y; A.z += T.z; A.w += T.w;}

__global__ __launch_bounds__(256, 4)
void fused_kernel(const float* __restrict__ nfeats,
                  const float* __restrict__ efeats,
                  const float* __restrict__ b_msg,
                  const float* __restrict__ b_apply,
                  float* __restrict__ out) {
    extern __shared__ float zb[];         // WPB * [128][ZSTRIDE]

    int tid = threadIdx.x;
    int lane = tid & 31;
    int wid = tid >> 5;

    float* z = zb + wid * (128 * ZSTRIDE);
    int base = blockIdx.x * NPB + wid * NPW;
    int q = lane & 15;
    bool isN = lane < 16;
    const float* fbase = isN ? nfeats : efeats;

    // Degree counts for this warp's 8 nodes: lane<8 loads, shfl per node.
    int cntreg = 0;
    {
        int vv = base + lane;
        if (vv >= N_NODES) vv = N_NODES - 1;
        if (lane < NPW) cntreg = __ldg(&g_count[vv]);
    }

    // ---- Gather: 2 rounds x 4 nodes; recs staged in z padding cols 8-9 ----
    #pragma unroll 1
    for (int rnd = 0; rnd < 2; rnd++) {
        __syncwarp();
        // stage 4 nodes' first-chunk records (slot = lane), 4 independent LDGs
        #pragma unroll
        for (int j2 = 0; j2 < 4; j2++) {
            int v = base + rnd * 4 + j2;
            if (v >= N_NODES) v = N_NODES - 1;
            int2 r = __ldg(&g_edges[(size_t)v * CAP + lane]);
            *(int2*)&z[(j2 * 32 + lane) * ZSTRIDE + 8] = r;
        }
        __syncwarp();

        #pragma unroll 1
        for (int j2 = 0; j2 < 4; j2++) {
            int j = rnd * 4 + j2;
            int v = base + j;
            if (v >= N_NODES) v = N_NODES - 1;
            size_t start = (size_t)v * CAP;
            int cnt = __shfl_sync(0xffffffffu, cntreg, j);
            if (cnt > CAP) cnt = CAP;

            float4 acc0 = make_float4(0.f, 0.f, 0.f, 0.f);
            float4 acc1 = make_float4(0.f, 0.f, 0.f, 0.f);

            int n0 = cnt < 32 ? cnt : 32;
            int jj = 0;
            #pragma unroll 1
            for (; jj + 4 <= n0; jj += 4) {
                int idx[4];
                #pragma unroll
                for (int u = 0; u < 4; u++) {
                    int2 r = *(const int2*)&z[(j2 * 32 + jj + u) * ZSTRIDE + 8];
                    idx[u] = isN ? r.y : r.x;
                }
                float4 t0, t1, t2, t3;
                {
                    const float4* p0 = (const float4*)(fbase + (size_t)idx[0] * D) + q;
                    const float4* p1 = (const float4*)(fbase + (size_t)idx[1] * D) + q;
                    const float4* p2 = (const float4*)(fbase + (size_t)idx[2] * D) + q;
                    const float4* p3 = (const float4*)(fbase + (size_t)idx[3] * D) + q;
                    t0 = isN ? __ldg(p0) : __ldcs(p0);
                    t1 = isN ? __ldg(p1) : __ldcs(p1);
                    t2 = isN ? __ldg(p2) : __ldcs(p2);
                    t3 = isN ? __ldg(p3) : __ldcs(p3);
                }
                ACC4(acc0, t0);
                ACC4(acc1, t1);
                ACC4(acc0, t2);
                ACC4(acc1, t3);
            }
            #pragma unroll 1
            for (; jj < n0; jj++) {
                int2 r = *(const int2*)&z[(j2 * 32 + jj) * ZSTRIDE + 8];
                int i0 = isN ? r.y : r.x;
                const float4* p = (const float4*)(fbase + (size_t)i0 * D) + q;
                float4 a = isN ? __ldg(p) : __ldcs(p);
                ACC4(acc0, a);
            }
            // rare tail: degree > 32 (old LDG + shfl path)
            #pragma unroll 1
            for (int b0 = 32; b0 < cnt; b0 += 32) {
                int n = cnt - b0;
                if (n > 32) n = 32;
                int2 rec = make_int2(0, 0);
                if (lane < n) rec = __ldg(&g_edges[start + b0 + lane]);
                int kk = 0;
                #pragma unroll 1
                for (; kk < n; kk++) {
                    int x0 = __shfl_sync(0xffffffffu, rec.x, kk);
                    int y0 = __shfl_sync(0xffffffffu, rec.y, kk);
                    const float4* p = (const float4*)(fbase + (size_t)(isN ? y0 : x0) * D) + q;
                    float4 a = isN ? __ldg(p) : __ldcs(p);
                    ACC4(acc0, a);
                }
            }

            acc0.x += acc1.x; acc0.y += acc1.y; acc0.z += acc1.z; acc0.w += acc1.w;
            int rowbase = (isN ? 0 : 64) + q * 4;
            z[(rowbase + 0) * ZSTRIDE + j] = acc0.x;
            z[(rowbase + 1) * ZSTRIDE + j] = acc0.y;
            z[(rowbase + 2) * ZSTRIDE + j] = acc0.z;
            z[(rowbase + 3) * ZSTRIDE + j] = acc0.w;
        }
    }
    __syncwarp();

    // ---- Phase A GEMM: msg linear on [Sn ; Se]; weights via LDG (L1) ----
    unsigned long long acc[2][4];
    #pragma unroll
    for (int g = 0; g < 2; g++)
        #pragma unroll
        for (int p = 0; p < 4; p++) acc[g][p] = 0ull;

    #pragma unroll 4
    for (int k = 0; k < 128; k++) {
        float2 wp = __ldg((const float2*)(g_WmT + k * 64) + lane);
        unsigned long long w0p, w1p;
        PACK2(w0p, wp.x);
        PACK2(w1p, wp.y);
        const unsigned long long* zr = (const unsigned long long*)(z + k * ZSTRIDE);
        #pragma unroll
        for (int p = 0; p < 4; p++) {
            unsigned long long s2 = zr[p];
            FMA2(acc[0][p], w0p, s2);
            FMA2(acc[1][p], w1p, s2);
        }
    }
    __syncwarp();

    // ---- h_neigh (mean + bias) + rebuild z for Phase B ----
    float bm0 = b_msg[lane], bm1 = b_msg[lane + 32];
    #pragma unroll
    for (int p = 0; p < 4; p++) {
        int v0 = base + 2 * p, v1 = base + 2 * p + 1;
        int c0 = v0 < N_NODES ? v0 : N_NODES - 1;
        int c1 = v1 < N_NODES ? v1 : N_NODES - 1;
        float d0 = (float)g_count[c0];
        float d1 = (float)g_count[c1];
        float i0 = d0 > 0.f ? 1.f / d0 : 0.f;
        float i1 = d1 > 0.f ? 1.f / d1 : 0.f;
        unsigned ux, uy;
        UNPACK2(ux, uy, acc[0][p]);
        float a0x = __uint_as_float(ux), a0y = __uint_as_float(uy);
        UNPACK2(ux, uy, acc[1][p]);
        float a1x = __uint_as_float(ux), a1y = __uint_as_float(uy);
        z[(64 + lane) * ZSTRIDE + 2 * p]     = d0 > 0.f ? a0x * i0 + bm0 : 0.f;
        z[(64 + lane) * ZSTRIDE + 2 * p + 1] = d1 > 0.f ? a0y * i1 + bm0 : 0.f;
        z[(96 + lane) * ZSTRIDE + 2 * p]     = d0 > 0.f ? a1x * i0 + bm1 : 0.f;
        z[(96 + lane) * ZSTRIDE + 2 * p + 1] = d1 > 0.f ? a1y * i1 + bm1 : 0.f;
    }
    #pragma unroll
    for (int j = 0; j < NPW; j++) {
        int v = base + j;
        if (v >= N_NODES) v = N_NODES - 1;
        const float* nf = nfeats + (size_t)v * D;
        z[(lane)      * ZSTRIDE + j] = nf[lane];
        z[(lane + 32) * ZSTRIDE + j] = nf[lane + 32];
    }
    __syncwarp();

    // ---- Phase B GEMM: apply linear on [self ; hn] ----
    #pragma unroll
    for (int g = 0; g < 2; g++)
        #pragma unroll
        for (int p = 0; p < 4; p++) acc[g][p] = 0ull;

    #pragma unroll 4
    for (int k = 0; k < 128; k++) {
        float2 wp = __ldg((const float2*)(g_WaT + k * 64) + lane);
        unsigned long long w0p, w1p;
        PACK2(w0p, wp.x);
        PACK2(w1p, wp.y);
        const unsigned long long* zr = (const unsigned long long*)(z + k * ZSTRIDE);
        #pragma unroll
        for (int p = 0; p < 4; p++) {
            unsigned long long s2 = zr[p];
            FMA2(acc[0][p], w0p, s2);
            FMA2(acc[1][p], w1p, s2);
        }
    }

    // ---- Epilogue: bias + relu + store ----
    float ba0 = b_apply[lane], ba1 = b_apply[lane + 32];
    #pragma unroll
    for (int p = 0; p < 4; p++) {
        int v0 = base + 2 * p, v1 = base + 2 * p + 1;
        unsigned ux, uy;
        UNPACK2(ux, uy, acc[0][p]);
        float a0x = __uint_as_float(ux), a0y = __uint_as_float(uy);
        UNPACK2(ux, uy, acc[1][p]);
        float a1x = __uint_as_float(ux), a1y = __uint_as_float(uy);
        if (v0 < N_NODES) {
            out[(size_t)v0 * D + lane]      = fmaxf(a0x + ba0, 0.f);
            out[(size_t)v0 * D + lane + 32] = fmaxf(a1x + ba1, 0.f);
        }
        if (v1 < N_NODES) {
            out[(size_t)v1 * D + lane]      = fmaxf(a0y + ba0, 0.f);
            out[(size_t)v1 * D + lane + 32] = fmaxf(a1y + ba1, 0.f);
        }
    }
}

// ---------------------------------------------------------------------------
#define NODE_SMEM ((WPB * 128 * ZSTRIDE) * (int)sizeof(float))

extern "C" void kernel_launch(void* const* d_in, const int* in_sizes, int n_in,
                              void* d_out, int out_size) {
    const float* nfeats  = (const float*)d_in[0];
    const float* efeats  = (const float*)d_in[1];
    const int*   src     = (const int*)d_in[2];
    const int*   dst     = (const int*)d_in[3];
    const float* W_msg   = (const float*)d_in[4];
    const float* b_msg   = (const float*)d_in[5];
    const float* W_apply = (const float*)d_in[6];
    const float* b_apply = (const float*)d_in[7];
    float* out = (float*)d_out;
    int E = in_sizes[2];

    cudaFuncSetAttribute(fused_kernel, cudaFuncAttributeMaxDynamicSharedMemorySize,
                         NODE_SMEM);

    void* cnt_ptr = nullptr;
    cudaGetSymbolAddress(&cnt_ptr, g_count);
    cudaMemsetAsync(cnt_ptr, 0, N_NODES * sizeof(int));

    build_kernel<<<(E + 255) / 256, 256>>>(src, dst, E, W_msg, W_apply);
    int nblocks = (N_NODES + NPB - 1) / NPB;
    fused_kernel<<<nblocks, 256, NODE_SMEM>>>(nfeats, efeats, b_msg, b_apply, out);
}

// round 13
// speedup vs baseline: 1.5199x; 1.0976x over previous
#include <cuda_runtime.h>
#include <cstdint>

#define N_NODES 50000
#define MAXE    800000
#define D       64
#define CAP     128   // max in-degree capacity (E/N=16, Poisson tail @128 ~ 1e-60)

// ---- scratch (device globals; no allocation allowed) ----
__device__ int   g_count[N_NODES];        // in-degree (memset to 0 each launch)
__device__ int2  g_edges[N_NODES * CAP];  // direct-placed (edge_id, src) records
__device__ float g_WmT[128 * 64];         // W_msg transposed+paired
__device__ float g_WaT[128 * 64];         // W_apply transposed+paired

// ---------------------------------------------------------------------------
// K1: build = histogram + direct placement; first 8K threads also transpose
// weights into paired layout WT[k*64 + (o&31)*2 + (o>>5)] = W[o*128+k].
// ---------------------------------------------------------------------------
__global__ void build_kernel(const int* __restrict__ src,
                             const int* __restrict__ dst, int E,
                             const float* __restrict__ W_msg,
                             const float* __restrict__ W_apply) {
    int e = blockIdx.x * blockDim.x + threadIdx.x;
    if (e < 64 * 128) {
        int o = e >> 7, k = e & 127;
        int slot = k * 64 + (o & 31) * 2 + (o >> 5);
        g_WmT[slot] = W_msg[e];
        g_WaT[slot] = W_apply[e];
    }
    if (e >= E) return;
    int d = dst[e];
    int r = atomicAdd(&g_count[d], 1);
    if (r < CAP) g_edges[(size_t)d * CAP + r] = make_int2(e, src[e]);
}

// ---------------------------------------------------------------------------
// K2: FUSED gather + node update.
// Change vs R12 (113us champion): feature-load inner loop unrolled 4 -> 8
// (8 outstanding LDG.128 per lane = 2x in-flight DRAM bytes), enabled by
// relaxing occupancy 4 -> 3 blocks/SM for the register headroom.
// Everything else byte-identical to R12.
// ---------------------------------------------------------------------------
#define ZSTRIDE 10
#define WPB 8
#define NPW 8
#define NPB (WPB * NPW)

#define PACK2(dst, f) asm("mov.b64 %0, {%1,%1};" : "=l"(dst) : "r"(__float_as_uint(f)))
#define UNPACK2(lo, hi, src) asm("mov.b64 {%0,%1}, %2;" : "=r"(lo), "=r"(hi) : "l"(src))
#define FMA2(acc, a, b) asm("fma.rn.f32x2 %0, %1, %2, %0;" : "+l"(acc) : "l"(a), "l"(b))
#define ACC4(A, T) {A.x += T.x; A.y += T.y; A.z += T.z; A.w += T.w;}

__global__ __launch_bounds__(256, 3)
void fused_kernel(const float* __restrict__ nfeats,
                  const float* __restrict__ efeats,
                  const float* __restrict__ b_msg,
                  const float* __restrict__ b_apply,
                  float* __restrict__ out) {
    extern __shared__ float zb[];         // WPB * [128][ZSTRIDE]

    int tid = threadIdx.x;
    int lane = tid & 31;
    int wid = tid >> 5;

    float* z = zb + wid * (128 * ZSTRIDE);
    int base = blockIdx.x * NPB + wid * NPW;
    int q = lane & 15;
    bool isN = lane < 16;
    const float* fbase = isN ? nfeats : efeats;

    // Degree counts for this warp's 8 nodes: lane<8 loads, shfl per node.
    int cntreg = 0;
    {
        int vv = base + lane;
        if (vv >= N_NODES) vv = N_NODES - 1;
        if (lane < NPW) cntreg = __ldg(&g_count[vv]);
    }

    // ---- Gather: 2 rounds x 4 nodes; recs staged in z padding cols 8-9 ----
    #pragma unroll 1
    for (int rnd = 0; rnd < 2; rnd++) {
        __syncwarp();
        // stage 4 nodes' first-chunk records (slot = lane), 4 independent LDGs
        #pragma unroll
        for (int j2 = 0; j2 < 4; j2++) {
            int v = base + rnd * 4 + j2;
            if (v >= N_NODES) v = N_NODES - 1;
            int2 r = __ldg(&g_edges[(size_t)v * CAP + lane]);
            *(int2*)&z[(j2 * 32 + lane) * ZSTRIDE + 8] = r;
        }
        __syncwarp();

        #pragma unroll 1
        for (int j2 = 0; j2 < 4; j2++) {
            int j = rnd * 4 + j2;
            int v = base + j;
            if (v >= N_NODES) v = N_NODES - 1;
            size_t start = (size_t)v * CAP;
            int cnt = __shfl_sync(0xffffffffu, cntreg, j);
            if (cnt > CAP) cnt = CAP;

            float4 acc0 = make_float4(0.f, 0.f, 0.f, 0.f);
            float4 acc1 = make_float4(0.f, 0.f, 0.f, 0.f);

            int n0 = cnt < 32 ? cnt : 32;
            int jj = 0;
            // 8-wide groups: 8 outstanding LDG.128 per lane
            #pragma unroll 1
            for (; jj + 8 <= n0; jj += 8) {
                int idx[8];
                #pragma unroll
                for (int u = 0; u < 8; u++) {
                    int2 r = *(const int2*)&z[(j2 * 32 + jj + u) * ZSTRIDE + 8];
                    idx[u] = isN ? r.y : r.x;
                }
                float4 t[8];
                #pragma unroll
                for (int u = 0; u < 8; u++) {
                    const float4* p = (const float4*)(fbase + (size_t)idx[u] * D) + q;
                    t[u] = isN ? __ldg(p) : __ldcs(p);
                }
                #pragma unroll
                for (int u = 0; u < 8; u += 2) {
                    ACC4(acc0, t[u]);
                    ACC4(acc1, t[u + 1]);
                }
            }
            // 4-wide group
            #pragma unroll 1
            for (; jj + 4 <= n0; jj += 4) {
                int idx[4];
                #pragma unroll
                for (int u = 0; u < 4; u++) {
                    int2 r = *(const int2*)&z[(j2 * 32 + jj + u) * ZSTRIDE + 8];
                    idx[u] = isN ? r.y : r.x;
                }
                float4 t0, t1, t2, t3;
                {
                    const float4* p0 = (const float4*)(fbase + (size_t)idx[0] * D) + q;
                    const float4* p1 = (const float4*)(fbase + (size_t)idx[1] * D) + q;
                    const float4* p2 = (const float4*)(fbase + (size_t)idx[2] * D) + q;
                    const float4* p3 = (const float4*)(fbase + (size_t)idx[3] * D) + q;
                    t0 = isN ? __ldg(p0) : __ldcs(p0);
                    t1 = isN ? __ldg(p1) : __ldcs(p1);
                    t2 = isN ? __ldg(p2) : __ldcs(p2);
                    t3 = isN ? __ldg(p3) : __ldcs(p3);
                }
                ACC4(acc0, t0);
                ACC4(acc1, t1);
                ACC4(acc0, t2);
                ACC4(acc1, t3);
            }
            #pragma unroll 1
            for (; jj < n0; jj++) {
                int2 r = *(const int2*)&z[(j2 * 32 + jj) * ZSTRIDE + 8];
                int i0 = isN ? r.y : r.x;
                const float4* p = (const float4*)(fbase + (size_t)i0 * D) + q;
                float4 a = isN ? __ldg(p) : __ldcs(p);
                ACC4(acc0, a);
            }
            // rare tail: degree > 32 (old LDG + shfl path)
            #pragma unroll 1
            for (int b0 = 32; b0 < cnt; b0 += 32) {
                int n = cnt - b0;
                if (n > 32) n = 32;
                int2 rec = make_int2(0, 0);
                if (lane < n) rec = __ldg(&g_edges[start + b0 + lane]);
                int kk = 0;
                #pragma unroll 1
                for (; kk < n; kk++) {
                    int x0 = __shfl_sync(0xffffffffu, rec.x, kk);
                    int y0 = __shfl_sync(0xffffffffu, rec.y, kk);
                    const float4* p = (const float4*)(fbase + (size_t)(isN ? y0 : x0) * D) + q;
                    float4 a = isN ? __ldg(p) : __ldcs(p);
                    ACC4(acc0, a);
                }
            }

            acc0.x += acc1.x; acc0.y += acc1.y; acc0.z += acc1.z; acc0.w += acc1.w;
            int rowbase = (isN ? 0 : 64) + q * 4;
            z[(rowbase + 0) * ZSTRIDE + j] = acc0.x;
            z[(rowbase + 1) * ZSTRIDE + j] = acc0.y;
            z[(rowbase + 2) * ZSTRIDE + j] = acc0.z;
            z[(rowbase + 3) * ZSTRIDE + j] = acc0.w;
        }
    }
    __syncwarp();

    // ---- Phase A GEMM: msg linear on [Sn ; Se]; weights via LDG (L1) ----
    unsigned long long acc[2][4];
    #pragma unroll
    for (int g = 0; g < 2; g++)
        #pragma unroll
        for (int p = 0; p < 4; p++) acc[g][p] = 0ull;

    #pragma unroll 4
    for (int k = 0; k < 128; k++) {
        float2 wp = __ldg((const float2*)(g_WmT + k * 64) + lane);
        unsigned long long w0p, w1p;
        PACK2(w0p, wp.x);
        PACK2(w1p, wp.y);
        const unsigned long long* zr = (const unsigned long long*)(z + k * ZSTRIDE);
        #pragma unroll
        for (int p = 0; p < 4; p++) {
            unsigned long long s2 = zr[p];
            FMA2(acc[0][p], w0p, s2);
            FMA2(acc[1][p], w1p, s2);
        }
    }
    __syncwarp();

    // ---- h_neigh (mean + bias) + rebuild z for Phase B ----
    float bm0 = b_msg[lane], bm1 = b_msg[lane + 32];
    #pragma unroll
    for (int p = 0; p < 4; p++) {
        int v0 = base + 2 * p, v1 = base + 2 * p + 1;
        int c0 = v0 < N_NODES ? v0 : N_NODES - 1;
        int c1 = v1 < N_NODES ? v1 : N_NODES - 1;
        float d0 = (float)g_count[c0];
        float d1 = (float)g_count[c1];
        float i0 = d0 > 0.f ? 1.f / d0 : 0.f;
        float i1 = d1 > 0.f ? 1.f / d1 : 0.f;
        unsigned ux, uy;
        UNPACK2(ux, uy, acc[0][p]);
        float a0x = __uint_as_float(ux), a0y = __uint_as_float(uy);
        UNPACK2(ux, uy, acc[1][p]);
        float a1x = __uint_as_float(ux), a1y = __uint_as_float(uy);
        z[(64 + lane) * ZSTRIDE + 2 * p]     = d0 > 0.f ? a0x * i0 + bm0 : 0.f;
        z[(64 + lane) * ZSTRIDE + 2 * p + 1] = d1 > 0.f ? a0y * i1 + bm0 : 0.f;
        z[(96 + lane) * ZSTRIDE + 2 * p]     = d0 > 0.f ? a1x * i0 + bm1 : 0.f;
        z[(96 + lane) * ZSTRIDE + 2 * p + 1] = d1 > 0.f ? a1y * i1 + bm1 : 0.f;
    }
    #pragma unroll
    for (int j = 0; j < NPW; j++) {
        int v = base + j;
        if (v >= N_NODES) v = N_NODES - 1;
        const float* nf = nfeats + (size_t)v * D;
        z[(lane)      * ZSTRIDE + j] = nf[lane];
        z[(lane + 32) * ZSTRIDE + j] = nf[lane + 32];
    }
    __syncwarp();

    // ---- Phase B GEMM: apply linear on [self ; hn] ----
    #pragma unroll
    for (int g = 0; g < 2; g++)
        #pragma unroll
        for (int p = 0; p < 4; p++) acc[g][p] = 0ull;

    #pragma unroll 4
    for (int k = 0; k < 128; k++) {
        float2 wp = __ldg((const float2*)(g_WaT + k * 64) + lane);
        unsigned long long w0p, w1p;
        PACK2(w0p, wp.x);
        PACK2(w1p, wp.y);
        const unsigned long long* zr = (const unsigned long long*)(z + k * ZSTRIDE);
        #pragma unroll
        for (int p = 0; p < 4; p++) {
            unsigned long long s2 = zr[p];
            FMA2(acc[0][p], w0p, s2);
            FMA2(acc[1][p], w1p, s2);
        }
    }

    // ---- Epilogue: bias + relu + store ----
    float ba0 = b_apply[lane], ba1 = b_apply[lane + 32];
    #pragma unroll
    for (int p = 0; p < 4; p++) {
        int v0 = base + 2 * p, v1 = base + 2 * p + 1;
        unsigned ux, uy;
        UNPACK2(ux, uy, acc[0][p]);
        float a0x = __uint_as_float(ux), a0y = __uint_as_float(uy);
        UNPACK2(ux, uy, acc[1][p]);
        float a1x = __uint_as_float(ux), a1y = __uint_as_float(uy);
        if (v0 < N_NODES) {
            out[(size_t)v0 * D + lane]      = fmaxf(a0x + ba0, 0.f);
            out[(size_t)v0 * D + lane + 32] = fmaxf(a1x + ba1, 0.f);
        }
        if (v1 < N_NODES) {
            out[(size_t)v1 * D + lane]      = fmaxf(a0y + ba0, 0.f);
            out[(size_t)v1 * D + lane + 32] = fmaxf(a1y + ba1, 0.f);
        }
    }
}

// ---------------------------------------------------------------------------
#define NODE_SMEM ((WPB * 128 * ZSTRIDE) * (int)sizeof(float))

extern "C" void kernel_launch(void* const* d_in, const int* in_sizes, int n_in,
                              void* d_out, int out_size) {
    const float* nfeats  = (const float*)d_in[0];
    const float* efeats  = (const float*)d_in[1];
    const int*   src     = (const int*)d_in[2];
    const int*   dst     = (const int*)d_in[3];
    const float* W_msg   = (const float*)d_in[4];
    const float* b_msg   = (const float*)d_in[5];
    const float* W_apply = (const float*)d_in[6];
    const float* b_apply = (const float*)d_in[7];
    float* out = (float*)d_out;
    int E = in_sizes[2];

    cudaFuncSetAttribute(fused_kernel, cudaFuncAttributeMaxDynamicSharedMemorySize,
                         NODE_SMEM);

    void* cnt_ptr = nullptr;
    cudaGetSymbolAddress(&cnt_ptr, g_count);
    cudaMemsetAsync(cnt_ptr, 0, N_NODES * sizeof(int));

    build_kernel<<<(E + 255) / 256, 256>>>(src, dst, E, W_msg, W_apply);
    int nblocks = (N_NODES + NPB - 1) / NPB;
    fused_kernel<<<nblocks, 256, NODE_SMEM>>>(nfeats, efeats, b_msg, b_apply, out);
}